// round 17
// baseline (speedup 1.0000x reference)
#include <cuda_runtime.h>
#include <cuda_bf16.h>
#include <math.h>

#define DD 32
#define NP 32768
#define HH 64
#define MM 8
#define LL 4
#define KK 48
#define NOUT 4096
#define GH1 512
#define GH2 256
#define CANDCAP 96
#define R2 0.0036f
#define PI2 6.283185307179586f
#define FSC (1.0f/32768.0f)
#define QPB 8          // queries per nbr block
#define H1S 68         // h1 smem row stride (conflict-free A frags)
#define H2K 260        // h2 [p][k] smem row stride (conflict-free A frags)

// ---------------- device scratch ----------------
__device__ float  g_x[NP*HH];
__device__ float  g_y[NP*HH];
__device__ float2 g_s1[DD*DD*MM*HH];
__device__ float2 g_s2[DD*16*MM*HH];
__device__ float2 g_s3[16*16*MM*HH];
__device__ float2 g_s4[16*16*MM*HH];
__device__ float2 g_i1[DD*16*MM*HH];
__device__ float2 g_i2[DD*DD*MM*HH];
__device__ int    g_nbr[NOUT*KK];
__device__ int    g_cnt[NOUT];
__device__ float  g_gno[NOUT*HH];
__device__ float  g_w2t[65536*2];   // packed tf32 w2: [kb(64)][n(256)][lr(4)] -> (k_lo,k_hi)
__device__ float  g_w3t[8192*2];    // packed tf32 w3: [kb(32)][n(64)][lr(4)] -> (k_lo,k_hi)

__device__ __forceinline__ float dgelu(float x){
    float u = 1.5957691216057308f*(x + 0.044715f*x*x*x);
    return x * __fdividef(1.f, 1.f + __expf(-u));
}

__device__ __forceinline__ void tw32(int m, float sign, float* s, float* c){
    int km = ((m & 31) + 15 & 31) - 15;
    __sincosf(sign*(PI2/32.f)*(float)km, s, c);
}

__device__ __forceinline__ unsigned f2tf32(float x){
    unsigned r;
    asm("cvt.rna.tf32.f32 %0, %1;" : "=r"(r) : "f"(x));
    return r;
}

__global__ void k_zero(float* out, int n){
    int i = blockIdx.x*256 + threadIdx.x;
    if (i < n) out[i] = 0.f;
}

// ---------------- weight pre-pack: tf32-rounded, fragment-paired ----------------
__global__ void __launch_bounds__(256) k_pack(const float* __restrict__ w2,
                                              const float* __restrict__ w3){
    int i = blockIdx.x*256 + threadIdx.x;
    if (i < 65536){
        int kb = i >> 10;
        int rem = i & 1023;
        int n = rem >> 2, lr = rem & 3;
        float a = w2[(kb*8+lr)*GH2 + n];
        float b = w2[(kb*8+lr+4)*GH2 + n];
        g_w2t[i*2]   = __uint_as_float(f2tf32(a));
        g_w2t[i*2+1] = __uint_as_float(f2tf32(b));
    } else if (i < 65536 + 8192){
        int j = i - 65536;
        int kb = j >> 8;
        int rem = j & 255;
        int n = rem >> 2, lr = rem & 3;
        float a = w3[(kb*8+lr)*64 + n];
        float b = w3[(kb*8+lr+4)*64 + n];
        g_w3t[j*2]   = __uint_as_float(f2tf32(a));
        g_w3t[j*2+1] = __uint_as_float(f2tf32(b));
    }
}

// ---------------- lift: 6 -> 256 (gelu) -> 64 ----------------
__global__ void __launch_bounds__(256) k_lift(const float* __restrict__ f,
                                              const float* __restrict__ in_p,
                                              const float* __restrict__ w1,
                                              const float* __restrict__ b1,
                                              const float* __restrict__ w2,
                                              const float* __restrict__ b2){
    __shared__ float s_in[8][6];
    __shared__ float s_h1[8*256];
    int t = threadIdx.x;
    int pb = blockIdx.x*8;
    if (t < 48){
        int pp = t/6, k = t%6;
        int p = pb + pp;
        s_in[pp][k] = (k < 3) ? f[p*3+k] : in_p[p*3+(k-3)];
    }
    __syncthreads();
    float bb = b1[t];
    for (int pp=0; pp<8; pp++){
        float h = bb;
        #pragma unroll
        for (int k=0;k<6;k++) h += s_in[pp][k]*w1[k*256+t];
        s_h1[pp*256+t] = dgelu(h);
    }
    __syncthreads();
    for (int r=0;r<2;r++){
        int e = t + r*256;
        int pp = e>>6, c = e&63;
        float acc = b2[c];
        const float* h1 = &s_h1[pp*256];
        for (int k=0;k<256;k++) acc += h1[k]*w2[k*64+c];
        g_x[(pb+pp)*64+c] = acc;
    }
}

// ---------------- forward z-DFT ----------------
__global__ void __launch_bounds__(256) k_fz(int sel){
    const float* cur = sel ? g_y : g_x;
    __shared__ float sx[32*64];
    __shared__ float twr[8*32], twi[8*32];
    int t = threadIdx.x, bx = blockIdx.x;
    for (int i=0;i<8;i++) sx[t+i*256] = cur[bx*2048 + t + i*256];
    {
        int kz = t>>5, z = t&31;
        float s,c; tw32(kz*z, -1.f, &s, &c);
        twr[t] = c*FSC; twi[t] = s*FSC;
    }
    __syncthreads();
    for (int r=0;r<2;r++){
        int e = t + r*256;
        int kz = e>>6, c = e&63;
        float re=0.f, im=0.f;
        #pragma unroll
        for (int z=0; z<32; z++){
            float v = sx[z*64+c];
            re += v*twr[kz*32+z];
            im += v*twi[kz*32+z];
        }
        g_s1[(bx*8+kz)*64+c] = make_float2(re, im);
    }
}

// ---------------- forward y-DFT (512 blocks) ----------------
__global__ void __launch_bounds__(256) k_fy(){
    __shared__ float2 sa[32*64];
    __shared__ float twr[16*32], twi[16*32];
    int t = threadIdx.x;
    int bx = blockIdx.x >> 1, half = blockIdx.x & 1;
    int ix = bx>>3, kz = bx&7;
    for (int i=0;i<8;i++){
        int e = t + i*256; int yy = e>>6, c = e&63;
        sa[e] = g_s1[((ix*32+yy)*8+kz)*64+c];
    }
    for (int i=0;i<2;i++){
        int e = t + i*256; int m = e>>5, yy = e&31;
        int k = (m<8)?m:(m+16);
        float s,c; tw32(k*yy, -1.f, &s, &c);
        twr[e]=c; twi[e]=s;
    }
    __syncthreads();
    for (int r=0;r<2;r++){
        int e = t + (half*2+r)*256;
        int m = e>>6, c = e&63;
        float re=0.f, im=0.f;
        #pragma unroll
        for (int yy=0;yy<32;yy++){
            float2 a = sa[yy*64+c];
            float wr = twr[m*32+yy], wi = twi[m*32+yy];
            re += a.x*wr - a.y*wi;
            im += a.x*wi + a.y*wr;
        }
        g_s2[((ix*16+m)*8+kz)*64+c] = make_float2(re, im);
    }
}

// ---------------- forward x-DFT (512 blocks) ----------------
__global__ void __launch_bounds__(256) k_fx(){
    __shared__ float2 sa[32*64];
    __shared__ float twr[16*32], twi[16*32];
    int t = threadIdx.x;
    int bb = blockIdx.x >> 2, quarter = blockIdx.x & 3;
    int ky = bb>>3, kz = bb&7;
    for (int i=0;i<8;i++){
        int e = t + i*256; int x = e>>6, c = e&63;
        sa[e] = g_s2[((x*16+ky)*8+kz)*64+c];
    }
    for (int i=0;i<2;i++){
        int e = t + i*256; int m = e>>5, x = e&31;
        int k = (m<8)?m:(m+16);
        float s,c; tw32(k*x, -1.f, &s, &c);
        twr[e]=c; twi[e]=s;
    }
    __syncthreads();
    {
        int e = t + quarter*256;
        int m = e>>6, c = e&63;
        float re=0.f, im=0.f;
        #pragma unroll
        for (int x=0;x<32;x++){
            float2 a = sa[x*64+c];
            float wr = twr[m*32+x], wi = twi[m*32+x];
            re += a.x*wr - a.y*wi;
            im += a.x*wi + a.y*wr;
        }
        g_s3[((m*16+ky)*8+kz)*64+c] = make_float2(re, im);
    }
}

// ---------------- spectral multiply, REAL weights; 512 blocks ----------------
__global__ void __launch_bounds__(256) k_spec(const float* __restrict__ W, int l){
    __shared__ float2 sx[64*8];
    int t = threadIdx.x, b = blockIdx.x;
    int half = b & 1, bb = b >> 1;
    int ci = bb>>6, mx = (bb>>3)&7, my = bb&7;
    int hx = ci>>1, hy = ci&1;
    int gx = mx + 8*hx, gy = my + 8*hy;
    for (int e = t; e < 512; e += 256){
        int i = e>>3, mz = e&7;
        sx[i*8+mz] = g_s3[((gx*16+gy)*8+mz)*64 + i];
    }
    __syncthreads();
    int mz = t&7, oh = (t>>3) + half*32;
    int moff = mx*64 + my*8 + mz;
    size_t base = (size_t)(l*4+ci)*64*64*512 + (size_t)moff + (size_t)oh*512;
    float ar=0.f, ai=0.f;
    #pragma unroll 8
    for (int i=0;i<64;i++){
        float2 xv = sx[i*8+mz];
        float w = W[base + (size_t)i*32768];
        ar += xv.x*w;  ai += xv.y*w;
    }
    g_s4[((gx*16+gy)*8+mz)*64 + oh] = make_float2(ar, ai);
}

// ---------------- inverse x (512 blocks) ----------------
__global__ void __launch_bounds__(256) k_ix(){
    __shared__ float2 sa[16*64];
    __shared__ float twr[16*32], twi[16*32];
    int t = threadIdx.x;
    int bb = blockIdx.x >> 2, quarter = blockIdx.x & 3;
    int ky = bb>>3, kz = bb&7;
    for (int i=0;i<4;i++){
        int e = t + i*256; int m = e>>6, c = e&63;
        sa[e] = g_s4[((m*16+ky)*8+kz)*64+c];
    }
    for (int i=0;i<2;i++){
        int e = t + i*256; int m = e>>5, x = e&31;
        int k = (m<8)?m:(m+16);
        float s,c; tw32(k*x, 1.f, &s, &c);
        twr[e]=c; twi[e]=s;
    }
    __syncthreads();
    for (int rr=0;rr<2;rr++){
        int e = t + (quarter*2+rr)*256;
        int x = e>>6, c = e&63;
        float re=0.f, im=0.f;
        #pragma unroll
        for (int m=0;m<16;m++){
            float2 a = sa[m*64+c];
            float wr = twr[m*32+x], wi = twi[m*32+x];
            re += a.x*wr - a.y*wi;
            im += a.x*wi + a.y*wr;
        }
        g_i1[((x*16+ky)*8+kz)*64+c] = make_float2(re, im);
    }
}

// ---------------- inverse y (512 blocks) ----------------
__global__ void __launch_bounds__(256) k_iy(){
    __shared__ float2 sa[16*64];
    __shared__ float twr[16*32], twi[16*32];
    int t = threadIdx.x;
    int bx = blockIdx.x >> 1, half = blockIdx.x & 1;
    int x = bx>>3, kz = bx&7;
    for (int i=0;i<4;i++){
        int e = t + i*256; int m = e>>6, c = e&63;
        sa[e] = g_i1[((x*16+m)*8+kz)*64+c];
    }
    for (int i=0;i<2;i++){
        int e = t + i*256; int m = e>>5, yy = e&31;
        int k = (m<8)?m:(m+16);
        float s,c; tw32(k*yy, 1.f, &s, &c);
        twr[e]=c; twi[e]=s;
    }
    __syncthreads();
    for (int rr=0;rr<4;rr++){
        int e = t + (half*4+rr)*256;
        int yy = e>>6, c = e&63;
        float re=0.f, im=0.f;
        #pragma unroll
        for (int m=0;m<16;m++){
            float2 a = sa[m*64+c];
            float wr = twr[m*32+yy], wi = twi[m*32+yy];
            re += a.x*wr - a.y*wi;
            im += a.x*wi + a.y*wr;
        }
        g_i2[((x*32+yy)*8+kz)*64+c] = make_float2(re, im);
    }
}

// ---------------- inverse z (c2r) + spec_b + skip GEMM + skip_b + gelu ----------------
__global__ void __launch_bounds__(256) k_iz(const float* __restrict__ spec_b,
                                            const float* __restrict__ skip_w,
                                            const float* __restrict__ skip_b,
                                            int l, int sel){
    const float* cur = sel ? g_y : g_x;
    float* dst = sel ? g_x : g_y;
    __shared__ float2 sza[8*64];
    __shared__ float  sxi[32*64];
    __shared__ float  ssw[64*64];
    __shared__ float  twr[8*32], twi[8*32];
    int t = threadIdx.x, bx = blockIdx.x;
    for (int i=0;i<2;i++){ int e=t+i*256; sza[e] = g_i2[(bx*8+(e>>6))*64+(e&63)]; }
    for (int i=0;i<8;i++)  sxi[t+i*256] = cur[bx*2048 + t + i*256];
    for (int i=0;i<16;i++) ssw[t+i*256] = skip_w[l*4096 + t + i*256];
    {
        int kz = t>>5, z = t&31;
        float s,c; tw32(kz*z, 1.f, &s, &c);
        twr[t]=c; twi[t]=s;
    }
    __syncthreads();
    for (int r=0;r<8;r++){
        int e = t + r*256;
        int z = e>>6, c = e&63;
        float acc = sza[c].x;
        #pragma unroll
        for (int k=1;k<8;k++){
            float2 a = sza[k*64+c];
            acc += 2.f*(a.x*twr[k*32+z] - a.y*twi[k*32+z]);
        }
        acc += spec_b[l*64+c] + skip_b[l*64+c];
        float sk = 0.f;
        #pragma unroll 8
        for (int j=0;j<64;j++) sk += sxi[z*64+j]*ssw[j*64+c];
        float v = acc + sk;
        if (l < 3) v = dgelu(v);
        dst[bx*2048 + z*64 + c] = v;
    }
}

// ---------------- neighbor search: 8 queries per block ----------------
__global__ void __launch_bounds__(128) k_nbr(const float* __restrict__ in_p,
                                             const float* __restrict__ out_p){
    __shared__ float s_d2[QPB][CANDCAP];
    __shared__ int   s_idx[QPB][CANDCAP];
    __shared__ int   s_n[QPB];
    __shared__ float s_q[QPB][3];
    int t = threadIdx.x;
    int q0 = blockIdx.x*QPB;
    if (t < QPB*3) s_q[t/3][t%3] = out_p[(q0 + t/3)*3 + (t%3)];
    if (t < QPB) s_n[t] = 0;
    __syncthreads();
    for (int p = t; p < NP; p += 128){
        float px = in_p[p*3+0], py = in_p[p*3+1], pz = in_p[p*3+2];
        #pragma unroll
        for (int qi=0; qi<QPB; qi++){
            float dx = s_q[qi][0]-px, dy = s_q[qi][1]-py, dz = s_q[qi][2]-pz;
            float d2 = dx*dx + dy*dy + dz*dz;
            if (d2 < R2){
                int pos = atomicAdd(&s_n[qi], 1);
                if (pos < CANDCAP){ s_d2[qi][pos] = d2; s_idx[qi][pos] = p; }
            }
        }
    }
    __syncthreads();
    if (t < QPB){
        int qi = t;
        int n = s_n[qi]; if (n > CANDCAP) n = CANDCAP;
        if (n > KK){
            for (int j = 0; j < KK; j++){
                int mi = j; float mv = s_d2[qi][j];
                for (int i = j+1; i < n; i++)
                    if (s_d2[qi][i] < mv){ mv = s_d2[qi][i]; mi = i; }
                float td = s_d2[qi][j]; s_d2[qi][j] = s_d2[qi][mi]; s_d2[qi][mi] = td;
                int   ti = s_idx[qi][j]; s_idx[qi][j] = s_idx[qi][mi]; s_idx[qi][mi] = ti;
            }
            n = KK;
        }
        g_cnt[q0 + qi] = n;
        s_n[qi] = n;
    }
    __syncthreads();
    for (int e = t; e < QPB*KK; e += 128){
        int qi = e / KK, j = e % KK;
        g_nbr[(q0+qi)*KK + j] = (j < s_n[qi]) ? s_idx[qi][j] : 0;
    }
}

// ---------------- GNO: 2 queries/block, tf32 mma layers 2+3, shared w2 reads ----------------
// dyn smem floats: h1c [96][H1S]=6528 (reused for a3), h2p [96][H2K]=24960 -> 125952 B
extern __shared__ float gno_dyn[];
__global__ void __launch_bounds__(512, 1) k_gno(const float* __restrict__ in_p,
                                                const float* __restrict__ out_p,
                                                const float* __restrict__ w1,
                                                const float* __restrict__ b1,
                                                const float* __restrict__ b2,
                                                const float* __restrict__ b3){
    float* s_h1c = gno_dyn;                 // [p96][H1S] tf32 bits; later a3 f32
    float* s_h2p = gno_dyn + 96*H1S;        // [p96][H2K] tf32 bits
    __shared__ float s_feat[96*6];
    __shared__ float s_red[512];
    __shared__ int   s_nn[2];
    int t = threadIdx.x, q0 = blockIdx.x*2;
    int warp = t>>5, lane = t&31;
    int g = lane>>2, lr = lane&3;
    if (t < 2) s_nn[t] = g_cnt[q0+t];
    if (t < 96){
        int qi = (t >= 48) ? 1 : 0;
        int p = t - 48*qi;
        int q = q0 + qi;
        int idx = g_nbr[q*KK + p];
        s_feat[t*6+0] = in_p[idx*3+0];
        s_feat[t*6+1] = in_p[idx*3+1];
        s_feat[t*6+2] = in_p[idx*3+2];
        s_feat[t*6+3] = out_p[q*3+0];
        s_feat[t*6+4] = out_p[q*3+1];
        s_feat[t*6+5] = out_p[q*3+2];
    }
    float acc[12][4];   // [mt(6)][nt(2)]
    #pragma unroll
    for (int i=0;i<12;i++){ acc[i][0]=0.f; acc[i][1]=0.f; acc[i][2]=0.f; acc[i][3]=0.f; }
    __syncthreads();
    int nn0 = s_nn[0], nn1 = s_nn[1];

    const float2* w2t = (const float2*)g_w2t;
    const float2* w3t = (const float2*)g_w3t;

    for (int cc = 0; cc < 8; cc++){
        // layer1: 96 rows x 64 k, 12 elements/thread
        for (int e = t; e < 96*64; e += 512){
            int p96 = e>>6, kk = e&63;
            int k = cc*64 + kk;
            int nn = (p96 >= 48) ? nn1 : nn0;
            int p = (p96 >= 48) ? (p96-48) : p96;
            float v = 0.f;
            if (p < nn){
                float h = b1[k];
                #pragma unroll
                for (int j=0;j<6;j++) h += s_feat[p96*6+j]*w1[j*GH1+k];
                v = __uint_as_float(f2tf32(dgelu(h)));
            }
            s_h1c[p96*H1S + kk] = v;
        }
        __syncthreads();
        // layer2: warp owns 16-wide n-slice for BOTH queries (6 m-tiles)
        #pragma unroll
        for (int kt=0; kt<8; kt++){
            int k0 = kt*8;
            int kb = cc*8 + kt;
            unsigned A[6][4];
            #pragma unroll
            for (int mt=0; mt<6; mt++){
                const float* ap = &s_h1c[(mt*16+g)*H1S + k0 + lr];
                A[mt][0] = __float_as_uint(ap[0]);
                A[mt][1] = __float_as_uint(ap[8*H1S]);
                A[mt][2] = __float_as_uint(ap[4]);
                A[mt][3] = __float_as_uint(ap[8*H1S+4]);
            }
            #pragma unroll
            for (int nt=0; nt<2; nt++){
                int n0 = warp*16 + nt*8;
                float2 bv = w2t[(size_t)(kb*GH2 + n0 + g)*4 + lr];
                unsigned B0 = __float_as_uint(bv.x);
                unsigned B1 = __float_as_uint(bv.y);
                #pragma unroll
                for (int mt=0; mt<6; mt++){
                    asm volatile(
                        "mma.sync.aligned.m16n8k8.row.col.f32.tf32.tf32.f32 "
                        "{%0,%1,%2,%3}, {%4,%5,%6,%7}, {%8,%9}, {%0,%1,%2,%3};"
                        : "+f"(acc[mt*2+nt][0]), "+f"(acc[mt*2+nt][1]),
                          "+f"(acc[mt*2+nt][2]), "+f"(acc[mt*2+nt][3])
                        : "r"(A[mt][0]), "r"(A[mt][1]), "r"(A[mt][2]), "r"(A[mt][3]),
                          "r"(B0), "r"(B1));
                }
            }
        }
        __syncthreads();
    }
    // layer2 epilogue: h2p[p96][n] = tf32(gelu(acc+b2)) masked
    #pragma unroll
    for (int mt=0; mt<6; mt++){
        int p0 = mt*16 + g, p1 = p0 + 8;
        int nn = (mt >= 3) ? nn1 : nn0;
        int pl0 = p0 - ((mt>=3)?48:0), pl1 = p1 - ((mt>=3)?48:0);
        float* r0 = &s_h2p[p0*H2K];
        float* r1 = &s_h2p[p1*H2K];
        #pragma unroll
        for (int nt=0; nt<2; nt++){
            int n0 = warp*16 + nt*8 + 2*lr;
            float b20 = b2[n0], b21 = b2[n0+1];
            r0[n0]   = (pl0 < nn) ? __uint_as_float(f2tf32(dgelu(acc[mt*2+nt][0] + b20))) : 0.f;
            r0[n0+1] = (pl0 < nn) ? __uint_as_float(f2tf32(dgelu(acc[mt*2+nt][1] + b21))) : 0.f;
            r1[n0]   = (pl1 < nn) ? __uint_as_float(f2tf32(dgelu(acc[mt*2+nt][2] + b20))) : 0.f;
            r1[n0+1] = (pl1 < nn) ? __uint_as_float(f2tf32(dgelu(acc[mt*2+nt][3] + b21))) : 0.f;
        }
    }
    __syncthreads();
    // layer3: warp (nt3 = warp&7, mh = warp>>3) -> 3 m-tiles of its query half
    float acc3[3][4];
    #pragma unroll
    for (int i=0;i<3;i++){ acc3[i][0]=0.f; acc3[i][1]=0.f; acc3[i][2]=0.f; acc3[i][3]=0.f; }
    int nt3 = warp & 7, mh = warp >> 3;
    #pragma unroll 8
    for (int kt=0; kt<32; kt++){
        int k0 = kt*8;
        unsigned A[3][4];
        #pragma unroll
        for (int j=0;j<3;j++){
            int mt = mh*3 + j;
            const float* ap = &s_h2p[(mt*16+g)*H2K + k0 + lr];
            A[j][0] = __float_as_uint(ap[0]);
            A[j][1] = __float_as_uint(ap[8*H2K]);
            A[j][2] = __float_as_uint(ap[4]);
            A[j][3] = __float_as_uint(ap[8*H2K+4]);
        }
        float2 bv = w3t[(size_t)(kt*64 + nt3*8 + g)*4 + lr];
        unsigned B0 = __float_as_uint(bv.x);
        unsigned B1 = __float_as_uint(bv.y);
        #pragma unroll
        for (int j=0;j<3;j++){
            asm volatile(
                "mma.sync.aligned.m16n8k8.row.col.f32.tf32.tf32.f32 "
                "{%0,%1,%2,%3}, {%4,%5,%6,%7}, {%8,%9}, {%0,%1,%2,%3};"
                : "+f"(acc3[j][0]), "+f"(acc3[j][1]),
                  "+f"(acc3[j][2]), "+f"(acc3[j][3])
                : "r"(A[j][0]), "r"(A[j][1]), "r"(A[j][2]), "r"(A[j][3]),
                  "r"(B0), "r"(B1));
        }
    }
    __syncthreads();   // done reading s_h2p; s_h1c reuse safe
    // store a3 into s_h1c as [p96][H1S] (c in 0..63)
    #pragma unroll
    for (int j=0;j<3;j++){
        int mt = mh*3 + j;
        int p0 = mt*16 + g, p1 = p0 + 8;
        int c0 = nt3*8 + 2*lr;
        s_h1c[p0*H1S + c0]   = acc3[j][0];
        s_h1c[p0*H1S + c0+1] = acc3[j][1];
        s_h1c[p1*H1S + c0]   = acc3[j][2];
        s_h1c[p1*H1S + c0+1] = acc3[j][3];
    }
    __syncthreads();
    // fy multiply + reduce: thread (qi = t>>8, c2, pg) owns 12 contiguous p
    {
        int qi = t >> 8, tt = t & 255;
        int c2 = tt & 63, pg = tt >> 6;
        int nn = qi ? nn1 : nn0;
        float local = 0.f;
        if (pg*12 < nn){
            float bb = b3[c2];
            #pragma unroll
            for (int j=0;j<12;j++){
                int p = pg*12 + j;
                if (p < nn){
                    int idx = g_nbr[(q0+qi)*KK + p];
                    local += (s_h1c[(qi*48+p)*H1S + c2] + bb) * g_x[idx*64 + c2];
                }
            }
        }
        s_red[qi*256 + pg*64 + c2] = local;
    }
    __syncthreads();
    if (t < 128){
        int qi = t >> 6, c = t & 63;
        const float* r = &s_red[qi*256];
        float s = r[c] + r[64+c] + r[128+c] + r[192+c];
        int nn = qi ? nn1 : nn0;
        g_gno[(q0+qi)*64 + c] = s / (float)(nn > 0 ? nn : 1);
    }
}

// ---------------- projection: 64 -> 256 (gelu) -> 1 ----------------
__global__ void __launch_bounds__(256) k_proj(const float* __restrict__ pw1,
                                              const float* __restrict__ pb1,
                                              const float* __restrict__ pw2,
                                              const float* __restrict__ pb2,
                                              float* __restrict__ out){
    __shared__ float s_g[32*64];
    __shared__ float s_h[32*256];
    int t = threadIdx.x, qb = blockIdx.x*32;
    for (int i=0;i<8;i++) s_g[t+i*256] = g_gno[qb*64 + t + i*256];
    __syncthreads();
    int c = t;
    float b = pb1[c], wv = pw2[c];
    for (int q=0;q<32;q++){
        float acc = b;
        #pragma unroll 8
        for (int j=0;j<64;j++) acc += s_g[q*64+j]*pw1[j*256+c];
        s_h[q*256+c] = dgelu(acc)*wv;
    }
    __syncthreads();
    if (t < 32){
        float s = pb2[0];
        const float* hr = &s_h[t*256];
        for (int k=0;k<256;k++) s += hr[k];
        out[qb + t] = s;
    }
}

// ---------------- launch ----------------
extern "C" void kernel_launch(void* const* d_in, const int* in_sizes, int n_in,
                              void* d_out, int out_size){
    static const int expA[21] = {98304,12288,98304,1536,256,16384,64,33554432,
                                 256,16384,256,3072,512,131072,256,16384,64,
                                 16384,256,256,1};
    float* out = (float*)d_out;
    int ok = (n_in == 21);
    for (int i = 0; i < 21 && ok; i++) if (in_sizes[i] != expA[i]) ok = 0;
    if (!ok){
        k_zero<<<(out_size + 255)/256, 256>>>(out, out_size);
        return;
    }

    const float* in_p  = (const float*)d_in[0];
    const float* out_p = (const float*)d_in[1];
    const float* f     = (const float*)d_in[2];
    const float* lw1   = (const float*)d_in[3];
    const float* lb1   = (const float*)d_in[4];
    const float* lw2   = (const float*)d_in[5];
    const float* lb2   = (const float*)d_in[6];
    const float* W     = (const float*)d_in[7];
    const float* specb = (const float*)d_in[8];
    const float* skw   = (const float*)d_in[9];
    const float* skb   = (const float*)d_in[10];
    const float* gw1   = (const float*)d_in[11];
    const float* gb1   = (const float*)d_in[12];
    const float* gw2   = (const float*)d_in[13];
    const float* gb2   = (const float*)d_in[14];
    const float* gw3   = (const float*)d_in[15];
    const float* gb3   = (const float*)d_in[16];
    const float* pw1   = (const float*)d_in[17];
    const float* pb1   = (const float*)d_in[18];
    const float* pw2   = (const float*)d_in[19];
    const float* pb2   = (const float*)d_in[20];

    int gno_smem = (96*H1S + 96*H2K) * (int)sizeof(float);  // 125952
    cudaFuncSetAttribute(k_gno, cudaFuncAttributeMaxDynamicSharedMemorySize, gno_smem);

    k_pack<<<288, 256>>>(gw2, gw3);
    k_lift<<<NP/8, 256>>>(f, in_p, lw1, lb1, lw2, lb2);
    for (int l = 0; l < LL; l++){
        int sel = l & 1;  // 0: read g_x write g_y; 1: read g_y write g_x
        k_fz<<<1024, 256>>>(sel);
        k_fy<<<512, 256>>>();
        k_fx<<<512, 256>>>();
        k_spec<<<512, 256>>>(W, l);
        k_ix<<<512, 256>>>();
        k_iy<<<512, 256>>>();
        k_iz<<<1024, 256>>>(specb, skw, skb, l, sel);
    }
    // latent now in g_x (l=3 writes g_x)
    k_nbr<<<NOUT/QPB, 128>>>(in_p, out_p);
    k_gno<<<NOUT/2, 512, gno_smem>>>(in_p, out_p, gw1, gb1, gb2, gb3);
    k_proj<<<NOUT/32, 256>>>(pw1, pb1, pw2, pb2, out);
}